// round 1
// baseline (speedup 1.0000x reference)
#include <cuda_runtime.h>
#include <math.h>

#define N_NODES 25600
#define N_EDGES 204800
#define ETOT    (N_EDGES + N_NODES)   // 230400 (self loops appended)
#define IN_CH   6
#define HID     64
#define HEADS   4
#define C1      (HEADS*HID)           // 256
#define G_GRAPHS 512
#define T_STEPS  50
#define OUT_DIM  30
#define NEG_SLOPE 0.2f
#define BN_INV 0.9999950000374996f    // 1/sqrt(1+1e-5)

// ---------------- scratch (device globals; no allocation allowed) ----------
__device__ __align__(16) float g_hproj1[N_NODES*C1];
__device__ float g_asrc1[N_NODES*HEADS];
__device__ float g_adst1[N_NODES*HEADS];
__device__ float g_emax1[N_NODES*HEADS];
__device__ __align__(16) float g_denom1[N_NODES*HEADS];
__device__ __align__(16) float g_accum1[N_NODES*C1];
__device__ __align__(16) float g_h1[N_NODES*C1];
__device__ __align__(16) float g_hproj2[N_NODES*HID];
__device__ float g_asrc2[N_NODES];
__device__ float g_adst2[N_NODES];
__device__ float g_emax2[N_NODES];
__device__ float g_denom2[N_NODES];
__device__ __align__(16) float g_accum2[N_NODES*HID];
__device__ __align__(16) float g_h2[N_NODES*HID];
__device__ __align__(16) float g_xgates[N_NODES*C1];   // layout (t, g, 256)

// ---------------- helpers ----------------
__device__ __forceinline__ float lrelu(float v) { return v > 0.f ? v : NEG_SLOPE*v; }
__device__ __forceinline__ float eluf(float v)  { return v > 0.f ? v : expm1f(v); }
__device__ __forceinline__ float sigf(float v)  { return 1.f/(1.f+expf(-v)); }

__device__ __forceinline__ void atomicMaxFloat(float* addr, float value) {
    if (value >= 0.f) atomicMax((int*)addr, __float_as_int(value));
    else              atomicMin((unsigned int*)addr, __float_as_uint(value));
}

__device__ __forceinline__ void redAdd4(float* addr, float a, float b, float c, float d) {
    asm volatile("red.global.add.v4.f32 [%0], {%1,%2,%3,%4};"
                 :: "l"(addr), "f"(a), "f"(b), "f"(c), "f"(d) : "memory");
}

// ---------------- kernels ----------------
__global__ void k_init() {
    int i = blockIdx.x*blockDim.x + threadIdx.x;
    if (i < N_NODES*C1)  g_accum1[i] = 0.f;
    if (i < N_NODES*HID) g_accum2[i] = 0.f;
    if (i < N_NODES*HEADS) { g_emax1[i] = __int_as_float(0xff800000); g_denom1[i] = 0.f; }
    if (i < N_NODES)       { g_emax2[i] = __int_as_float(0xff800000); g_denom2[i] = 0.f; }
}

// hproj1 = x @ W1 ; asrc1/adst1 per-node attention dots. 1 block = 1 node.
__global__ void k_proj1(const float* __restrict__ x, const float* __restrict__ W1,
                        const float* __restrict__ as1, const float* __restrict__ ad1) {
    __shared__ float W1s[IN_CH*C1];
    __shared__ float as_s[C1], ad_s[C1];
    __shared__ float redS[8], redD[8];
    int n = blockIdx.x;
    int t = threadIdx.x;
    for (int i = t; i < IN_CH*C1; i += 256) W1s[i] = W1[i];
    as_s[t] = as1[t]; ad_s[t] = ad1[t];
    __syncthreads();
    float v = 0.f;
    #pragma unroll
    for (int k = 0; k < IN_CH; k++) v += x[n*IN_CH + k] * W1s[k*C1 + t];
    g_hproj1[n*C1 + t] = v;
    float s = v * as_s[t], d = v * ad_s[t];
    #pragma unroll
    for (int o = 16; o; o >>= 1) { s += __shfl_down_sync(~0u, s, o); d += __shfl_down_sync(~0u, d, o); }
    int w = t >> 5;
    if ((t & 31) == 0) { redS[w] = s; redD[w] = d; }
    __syncthreads();
    if (t < HEADS) {
        g_asrc1[n*HEADS + t] = redS[2*t] + redS[2*t+1];
        g_adst1[n*HEADS + t] = redD[2*t] + redD[2*t+1];
    }
}

__global__ void k_emax1(const int* __restrict__ ei) {
    int i = blockIdx.x*blockDim.x + threadIdx.x;
    if (i >= ETOT*HEADS) return;
    int e = i >> 2, h = i & 3;
    int s, d;
    if (e < N_EDGES) { s = ei[e]; d = ei[N_EDGES + e]; } else { s = d = e - N_EDGES; }
    atomicMaxFloat(&g_emax1[d*4 + h], lrelu(g_asrc1[s*4 + h] + g_adst1[d*4 + h]));
}

// one warp per edge: denom += ex ; accum[dst] += ex * hproj1[src]
__global__ void k_esum1(const int* __restrict__ ei) {
    int gt = blockIdx.x*blockDim.x + threadIdx.x;
    int e = gt >> 5, lane = gt & 31;
    if (e >= ETOT) return;
    int s, d;
    if (e < N_EDGES) { s = ei[e]; d = ei[N_EDGES + e]; } else { s = d = e - N_EDGES; }
    float ex[4];
    #pragma unroll
    for (int h = 0; h < 4; h++) {
        float sc = lrelu(g_asrc1[s*4 + h] + g_adst1[d*4 + h]);
        ex[h] = expf(sc - g_emax1[d*4 + h]);
    }
    if (lane == 0) redAdd4(&g_denom1[d*4], ex[0], ex[1], ex[2], ex[3]);
    int c1 = lane*4, c2 = 128 + lane*4;
    float4 v1 = *(const float4*)&g_hproj1[s*C1 + c1];
    float4 v2 = *(const float4*)&g_hproj1[s*C1 + c2];
    float w1 = ex[c1 >> 6], w2 = ex[c2 >> 6];
    redAdd4(&g_accum1[d*C1 + c1], v1.x*w1, v1.y*w1, v1.z*w1, v1.w*w1);
    redAdd4(&g_accum1[d*C1 + c2], v2.x*w2, v2.y*w2, v2.z*w2, v2.w*w2);
}

__global__ void k_fin1(const float* __restrict__ b1, const float* __restrict__ g1,
                       const float* __restrict__ be1) {
    int i = blockIdx.x*blockDim.x + threadIdx.x;
    if (i >= N_NODES*C1) return;
    int n = i >> 8, c = i & 255, h = c >> 6;
    float v = g_accum1[i] / g_denom1[n*4 + h] + b1[c];
    v = g1[c]*(v*BN_INV) + be1[c];
    g_h1[i] = eluf(v);
}

// hproj2 = h1 @ W2 (256 -> 64). 16 nodes per block, W2 resident in smem.
#define NPB2 16
__global__ void k_proj2(const float* __restrict__ W2) {
    extern __shared__ float sm[];
    float* W2s = sm;               // 256*64
    float* h1s = sm + 256*64;      // NPB2*256
    int t = threadIdx.x;
    int nbase = blockIdx.x * NPB2;
    for (int i = t; i < 256*64; i += 256) W2s[i] = W2[i];
    for (int i = t; i < NPB2*256; i += 256) h1s[i] = g_h1[nbase*256 + i];
    __syncthreads();
    int j = t & 63, slot = t >> 6;
    float acc[4] = {0.f, 0.f, 0.f, 0.f};
    for (int k = 0; k < 256; k++) {
        float w = W2s[k*64 + j];
        #pragma unroll
        for (int q = 0; q < 4; q++) acc[q] += w * h1s[(slot + 4*q)*256 + k];
    }
    #pragma unroll
    for (int q = 0; q < 4; q++) g_hproj2[(nbase + slot + 4*q)*64 + j] = acc[q];
}

// per-node attention dots for layer 2 (1 head). warp per node.
__global__ void k_att2(const float* __restrict__ as2, const float* __restrict__ ad2) {
    int gt = blockIdx.x*blockDim.x + threadIdx.x;
    int n = gt >> 5, l = gt & 31;
    if (n >= N_NODES) return;
    float v1 = g_hproj2[n*64 + l], v2 = g_hproj2[n*64 + 32 + l];
    float s = v1*as2[l] + v2*as2[32 + l];
    float d = v1*ad2[l] + v2*ad2[32 + l];
    #pragma unroll
    for (int o = 16; o; o >>= 1) { s += __shfl_down_sync(~0u, s, o); d += __shfl_down_sync(~0u, d, o); }
    if (l == 0) { g_asrc2[n] = s; g_adst2[n] = d; }
}

__global__ void k_emax2(const int* __restrict__ ei) {
    int e = blockIdx.x*blockDim.x + threadIdx.x;
    if (e >= ETOT) return;
    int s, d;
    if (e < N_EDGES) { s = ei[e]; d = ei[N_EDGES + e]; } else { s = d = e - N_EDGES; }
    atomicMaxFloat(&g_emax2[d], lrelu(g_asrc2[s] + g_adst2[d]));
}

// 16 threads per edge
__global__ void k_esum2(const int* __restrict__ ei) {
    int gt = blockIdx.x*blockDim.x + threadIdx.x;
    int e = gt >> 4, q = gt & 15;
    if (e >= ETOT) return;
    int s, d;
    if (e < N_EDGES) { s = ei[e]; d = ei[N_EDGES + e]; } else { s = d = e - N_EDGES; }
    float ex = expf(lrelu(g_asrc2[s] + g_adst2[d]) - g_emax2[d]);
    if (q == 0) atomicAdd(&g_denom2[d], ex);
    int c = q*4;
    float4 v = *(const float4*)&g_hproj2[s*64 + c];
    redAdd4(&g_accum2[d*64 + c], v.x*ex, v.y*ex, v.z*ex, v.w*ex);
}

__global__ void k_fin2(const float* __restrict__ b2, const float* __restrict__ g2,
                       const float* __restrict__ be2) {
    int i = blockIdx.x*blockDim.x + threadIdx.x;
    if (i >= N_NODES*HID) return;
    int n = i >> 6, c = i & 63;
    float v = g_accum2[i] / g_denom2[n] + b2[c];
    v = g2[c]*(v*BN_INV) + be2[c];
    g_h2[i] = eluf(v);
}

// xgates[(t,g),j] = h2 @ Wih.T + bih + bhh, scattered to (node_time, batch) slot.
#define NPB3 8
__global__ void k_xgates(const float* __restrict__ Wih, const float* __restrict__ bih,
                         const float* __restrict__ bhh, const int* __restrict__ batch,
                         const int* __restrict__ ntime) {
    extern __shared__ float sm[];
    float* Ws  = sm;             // 64*257 transposed, padded
    float* h2s = sm + 64*257;    // NPB3*64
    int t = threadIdx.x;
    int nbase = blockIdx.x * NPB3;
    for (int i = t; i < 256*64; i += 256) { int j = i >> 6, k = i & 63; Ws[k*257 + j] = Wih[i]; }
    for (int i = t; i < NPB3*64; i += 256) h2s[i] = g_h2[nbase*64 + i];
    __syncthreads();
    float acc[NPB3];
    #pragma unroll
    for (int q = 0; q < NPB3; q++) acc[q] = 0.f;
    for (int k = 0; k < 64; k++) {
        float w = Ws[k*257 + t];
        #pragma unroll
        for (int q = 0; q < NPB3; q++) acc[q] += w * h2s[q*64 + k];
    }
    float bb = bih[t] + bhh[t];
    #pragma unroll
    for (int q = 0; q < NPB3; q++) {
        int n = nbase + q;
        int dest = (ntime[n]*G_GRAPHS + batch[n])*C1 + t;
        g_xgates[dest] = acc[q] + bb;
    }
}

// one block per graph; 50 sequential steps entirely on-chip; fused final FC.
__global__ void k_lstm(const float* __restrict__ Whh, const float* __restrict__ Wfc,
                       const float* __restrict__ bfc, float* __restrict__ out) {
    extern __shared__ float sm[];
    float* Ws   = sm;              // 64*257 transposed Whh
    float* hh   = sm + 64*257;     // 64
    float* gate = hh + 64;         // 256
    int t = threadIdx.x;
    int g = blockIdx.x;
    for (int i = t; i < 256*64; i += 256) { int j = i >> 6, k = i & 63; Ws[k*257 + j] = Whh[i]; }
    if (t < 64) hh[t] = 0.f;
    float c = 0.f;
    __syncthreads();
    for (int step = 0; step < T_STEPS; step++) {
        float dot = g_xgates[(step*G_GRAPHS + g)*C1 + t];
        #pragma unroll 8
        for (int k = 0; k < 64; k++) dot += hh[k] * Ws[k*257 + t];
        gate[t] = dot;
        __syncthreads();
        if (t < 64) {
            float ig = gate[t], fg = gate[t+64], gg = gate[t+128], og = gate[t+192];
            c = sigf(fg)*c + sigf(ig)*tanhf(gg);
            hh[t] = sigf(og)*tanhf(c);
        }
        __syncthreads();
    }
    if (t < OUT_DIM) {
        float acc = bfc[t];
        #pragma unroll 8
        for (int k = 0; k < 64; k++) acc += hh[k] * Wfc[k*OUT_DIM + t];
        out[g*OUT_DIM + t] = acc;
    }
}

// ---------------- launch ----------------
static const int SMEM_PROJ2 = (256*64 + NPB2*256) * 4;           // 80 KB
static const int SMEM_XG    = (64*257 + NPB3*64) * 4;            // ~68 KB
static const int SMEM_LSTM  = (64*257 + 64 + 256) * 4;           // ~67 KB

extern "C" void kernel_launch(void* const* d_in, const int* in_sizes, int n_in,
                              void* d_out, int out_size) {
    const float* x    = (const float*)d_in[0];
    const int*   ei   = (const int*)  d_in[1];
    const int*   batch= (const int*)  d_in[2];
    const int*   ntime= (const int*)  d_in[3];
    const float* W1   = (const float*)d_in[4];
    const float* as1  = (const float*)d_in[5];
    const float* ad1  = (const float*)d_in[6];
    const float* b1   = (const float*)d_in[7];
    const float* g1   = (const float*)d_in[8];
    const float* be1  = (const float*)d_in[9];
    const float* W2   = (const float*)d_in[10];
    const float* as2  = (const float*)d_in[11];
    const float* ad2  = (const float*)d_in[12];
    const float* b2   = (const float*)d_in[13];
    const float* g2   = (const float*)d_in[14];
    const float* be2  = (const float*)d_in[15];
    const float* Wih  = (const float*)d_in[16];
    const float* Whh  = (const float*)d_in[17];
    const float* bih  = (const float*)d_in[18];
    const float* bhh  = (const float*)d_in[19];
    const float* Wfc  = (const float*)d_in[20];
    const float* bfc  = (const float*)d_in[21];
    float* out = (float*)d_out;

    cudaFuncSetAttribute(k_proj2,  cudaFuncAttributeMaxDynamicSharedMemorySize, SMEM_PROJ2);
    cudaFuncSetAttribute(k_xgates, cudaFuncAttributeMaxDynamicSharedMemorySize, SMEM_XG);
    cudaFuncSetAttribute(k_lstm,   cudaFuncAttributeMaxDynamicSharedMemorySize, SMEM_LSTM);

    k_init  <<<(N_NODES*C1 + 255)/256, 256>>>();
    k_proj1 <<<N_NODES, 256>>>(x, W1, as1, ad1);
    k_emax1 <<<(ETOT*4 + 255)/256, 256>>>(ei);
    k_esum1 <<<(ETOT*32 + 255)/256, 256>>>(ei);
    k_fin1  <<<(N_NODES*C1 + 255)/256, 256>>>(b1, g1, be1);
    k_proj2 <<<N_NODES/NPB2, 256, SMEM_PROJ2>>>(W2);
    k_att2  <<<(N_NODES*32 + 255)/256, 256>>>(as2, ad2);
    k_emax2 <<<(ETOT + 255)/256, 256>>>(ei);
    k_esum2 <<<(ETOT*16 + 255)/256, 256>>>(ei);
    k_fin2  <<<(N_NODES*HID + 255)/256, 256>>>(b2, g2, be2);
    k_xgates<<<N_NODES/NPB3, 256, SMEM_XG>>>(Wih, bih, bhh, batch, ntime);
    k_lstm  <<<G_GRAPHS, 256, SMEM_LSTM>>>(Whh, Wfc, bfc, out);
}

// round 2
// speedup vs baseline: 1.7486x; 1.7486x over previous
#include <cuda_runtime.h>
#include <math.h>

#define N_NODES 25600
#define N_EDGES 204800
#define ETOT    (N_EDGES + N_NODES)   // 230400 (self loops appended)
#define IN_CH   6
#define HID     64
#define HEADS   4
#define C1      (HEADS*HID)           // 256
#define G_GRAPHS 512
#define T_STEPS  50
#define OUT_DIM  30
#define NEG_SLOPE 0.2f
#define BN_INV 0.9999950000374996f    // 1/sqrt(1+1e-5)

// ---------------- scratch (device globals; no allocation allowed) ----------
__device__ float g_wsrc[24];                      // [k][h] k<6,h<4
__device__ float g_wdst[24];
__device__ __align__(16) float g_asrc1[N_NODES*HEADS];
__device__ __align__(16) float g_adst1[N_NODES*HEADS];
__device__ __align__(16) float g_denom1[N_NODES*HEADS];
__device__ __align__(16) float g_xagg[N_NODES*32];     // per node 4 heads x 8 (6 used)
__device__ __align__(16) float g_h1[N_NODES*C1];
__device__ __align__(16) float g_hproj2[N_NODES*HID];
__device__ float g_asrc2[N_NODES];
__device__ float g_adst2[N_NODES];
__device__ float g_denom2[N_NODES];
__device__ __align__(16) float g_accum2[N_NODES*HID];
__device__ __align__(16) float g_h2[N_NODES*HID];
__device__ __align__(16) float g_xgates[N_NODES*C1];   // layout (t, g, 256)

// ---------------- helpers ----------------
__device__ __forceinline__ float lrelu(float v) { return v > 0.f ? v : NEG_SLOPE*v; }
__device__ __forceinline__ float eluf(float v)  { return v > 0.f ? v : expm1f(v); }
__device__ __forceinline__ float sigf(float v)  { return 1.f/(1.f+expf(-v)); }

__device__ __forceinline__ void redAdd4(float* addr, float a, float b, float c, float d) {
    asm volatile("red.global.add.v4.f32 [%0], {%1,%2,%3,%4};"
                 :: "l"(addr), "f"(a), "f"(b), "f"(c), "f"(d) : "memory");
}
__device__ __forceinline__ void redAdd2(float* addr, float a, float b) {
    asm volatile("red.global.add.v2.f32 [%0], {%1,%2};"
                 :: "l"(addr), "f"(a), "f"(b) : "memory");
}

// ---------------- kernels ----------------
__global__ void k_init() {
    int i = blockIdx.x*blockDim.x + threadIdx.x;
    if (i < N_NODES*32)    g_xagg[i] = 0.f;
    if (i < N_NODES*HEADS) g_denom1[i] = 0.f;
    if (i < N_NODES*HID)   g_accum2[i] = 0.f;
    if (i < N_NODES)       g_denom2[i] = 0.f;
}

// wsrc[k][h] = sum_c W1[k, h*64+c]*att_src[h,c]  (and wdst)
__global__ void k_pre1(const float* __restrict__ W1, const float* __restrict__ as1,
                       const float* __restrict__ ad1) {
    int t = threadIdx.x;
    if (t < 24) {
        int k = t >> 2, h = t & 3;
        float s = 0.f;
        for (int c = 0; c < 64; c++) s += W1[k*C1 + h*64 + c] * as1[h*64 + c];
        g_wsrc[t] = s;
    } else if (t >= 32 && t < 56) {
        int i = t - 32, k = i >> 2, h = i & 3;
        float s = 0.f;
        for (int c = 0; c < 64; c++) s += W1[k*C1 + h*64 + c] * ad1[h*64 + c];
        g_wdst[i] = s;
    }
}

// per-node attention dots: asrc1 = x @ wsrc, adst1 = x @ wdst  (N x 4 each)
__global__ void k_att1(const float* __restrict__ x) {
    int n = blockIdx.x*blockDim.x + threadIdx.x;
    if (n >= N_NODES) return;
    float xv[IN_CH];
    #pragma unroll
    for (int k = 0; k < IN_CH; k++) xv[k] = x[n*IN_CH + k];
    float s[4] = {0,0,0,0}, d[4] = {0,0,0,0};
    #pragma unroll
    for (int k = 0; k < IN_CH; k++) {
        #pragma unroll
        for (int h = 0; h < 4; h++) {
            s[h] += xv[k]*g_wsrc[k*4+h];
            d[h] += xv[k]*g_wdst[k*4+h];
        }
    }
    *(float4*)&g_asrc1[n*4] = make_float4(s[0],s[1],s[2],s[3]);
    *(float4*)&g_adst1[n*4] = make_float4(d[0],d[1],d[2],d[3]);
}

// per edge: ex[h] = exp(lrelu(asrc+adst)); denom += ex; xagg[dst] += ex * x[src]
__global__ void k_esum1(const int* __restrict__ ei, const float* __restrict__ x) {
    int e = blockIdx.x*blockDim.x + threadIdx.x;
    if (e >= ETOT) return;
    int s, d;
    if (e < N_EDGES) { s = ei[e]; d = ei[N_EDGES + e]; } else { s = d = e - N_EDGES; }
    float4 as = *(const float4*)&g_asrc1[s*4];
    float4 ad = *(const float4*)&g_adst1[d*4];
    float ex[4];
    ex[0] = expf(lrelu(as.x + ad.x));
    ex[1] = expf(lrelu(as.y + ad.y));
    ex[2] = expf(lrelu(as.z + ad.z));
    ex[3] = expf(lrelu(as.w + ad.w));
    redAdd4(&g_denom1[d*4], ex[0], ex[1], ex[2], ex[3]);
    float xv[IN_CH];
    #pragma unroll
    for (int k = 0; k < IN_CH; k++) xv[k] = x[s*IN_CH + k];
    float* base = &g_xagg[d*32];
    #pragma unroll
    for (int h = 0; h < 4; h++) {
        float w = ex[h];
        redAdd4(base + h*8,     w*xv[0], w*xv[1], w*xv[2], w*xv[3]);
        redAdd2(base + h*8 + 4, w*xv[4], w*xv[5]);
    }
}

// h1[n,c] = elu(bn((xagg[n,h,:]/denom) @ W1[:,c] + b1[c]))
__global__ void k_fin1(const float* __restrict__ W1, const float* __restrict__ b1,
                       const float* __restrict__ g1, const float* __restrict__ be1) {
    int i = blockIdx.x*blockDim.x + threadIdx.x;
    if (i >= N_NODES*C1) return;
    int n = i >> 8, c = i & 255, h = c >> 6;
    float inv = 1.f / g_denom1[n*4 + h];
    const float* xa = &g_xagg[n*32 + h*8];
    float v = 0.f;
    #pragma unroll
    for (int k = 0; k < IN_CH; k++) v += xa[k] * W1[k*C1 + c];
    v = v*inv + b1[c];
    v = g1[c]*(v*BN_INV) + be1[c];
    g_h1[i] = eluf(v);
}

// GEMM: hproj2 = h1(25600x256) @ W2(256x64). 64 nodes/block, 4x4 per-thread tile.
__global__ void k_proj2(const float* __restrict__ W2) {
    extern __shared__ float sm[];
    float* W2s = sm;            // [256][64]
    float* h1s = sm + 256*64;   // [64][260] padded
    int t = threadIdx.x;
    int cg = t & 15, ng = t >> 4;       // 16 col-groups x 16 node-groups
    int nbase = blockIdx.x * 64;
    for (int i = t; i < 256*64; i += 256) W2s[i] = W2[i];
    for (int i = t; i < 64*256; i += 256) {
        int n = i >> 8, k = i & 255;
        h1s[n*260 + k] = g_h1[(nbase + n)*256 + k];
    }
    __syncthreads();
    float acc[4][4];
    #pragma unroll
    for (int q = 0; q < 4; q++) { acc[q][0]=0; acc[q][1]=0; acc[q][2]=0; acc[q][3]=0; }
    int j0 = cg*4;
    for (int k = 0; k < 256; k++) {
        float4 w = *(const float4*)&W2s[k*64 + j0];
        #pragma unroll
        for (int q = 0; q < 4; q++) {
            float hv = h1s[(ng*4 + q)*260 + k];
            acc[q][0] += hv*w.x; acc[q][1] += hv*w.y;
            acc[q][2] += hv*w.z; acc[q][3] += hv*w.w;
        }
    }
    #pragma unroll
    for (int q = 0; q < 4; q++) {
        int n = nbase + ng*4 + q;
        *(float4*)&g_hproj2[n*64 + j0] = make_float4(acc[q][0],acc[q][1],acc[q][2],acc[q][3]);
    }
}

// per-node attention dots for layer 2 (1 head). warp per node.
__global__ void k_att2(const float* __restrict__ as2, const float* __restrict__ ad2) {
    int gt = blockIdx.x*blockDim.x + threadIdx.x;
    int n = gt >> 5, l = gt & 31;
    if (n >= N_NODES) return;
    float v1 = g_hproj2[n*64 + l], v2 = g_hproj2[n*64 + 32 + l];
    float s = v1*as2[l] + v2*as2[32 + l];
    float d = v1*ad2[l] + v2*ad2[32 + l];
    #pragma unroll
    for (int o = 16; o; o >>= 1) { s += __shfl_down_sync(~0u, s, o); d += __shfl_down_sync(~0u, d, o); }
    if (l == 0) { g_asrc2[n] = s; g_adst2[n] = d; }
}

// 16 threads per edge: denom += ex ; accum2[dst] += ex * hproj2[src]
__global__ void k_esum2(const int* __restrict__ ei) {
    int gt = blockIdx.x*blockDim.x + threadIdx.x;
    int e = gt >> 4, q = gt & 15;
    if (e >= ETOT) return;
    int s, d;
    if (e < N_EDGES) { s = ei[e]; d = ei[N_EDGES + e]; } else { s = d = e - N_EDGES; }
    float ex = expf(lrelu(g_asrc2[s] + g_adst2[d]));
    if (q == 0) atomicAdd(&g_denom2[d], ex);
    int c = q*4;
    float4 v = *(const float4*)&g_hproj2[s*64 + c];
    redAdd4(&g_accum2[d*64 + c], v.x*ex, v.y*ex, v.z*ex, v.w*ex);
}

__global__ void k_fin2(const float* __restrict__ b2, const float* __restrict__ g2,
                       const float* __restrict__ be2) {
    int i = blockIdx.x*blockDim.x + threadIdx.x;
    if (i >= N_NODES*HID) return;
    int n = i >> 6, c = i & 63;
    float v = g_accum2[i] / g_denom2[n] + b2[c];
    v = g2[c]*(v*BN_INV) + be2[c];
    g_h2[i] = eluf(v);
}

// GEMM: xgates = h2(25600x64) @ Wih^T(64x256) + bih + bhh, rows scattered to (time,graph)
__global__ void k_xgates(const float* __restrict__ Wih, const float* __restrict__ bih,
                         const float* __restrict__ bhh, const int* __restrict__ batch,
                         const int* __restrict__ ntime) {
    extern __shared__ float sm[];
    float* WT  = sm;            // [64 k][260 pad] = Wih^T
    float* h2s = sm + 64*260;   // [32][68 pad]
    int t = threadIdx.x;
    int cg = t & 63, ng = t >> 6;       // 64 col-groups x 4 node-groups
    int nbase = blockIdx.x * 32;
    for (int i = t; i < 256*64; i += 256) {
        int j = i >> 6, k = i & 63;
        WT[k*260 + j] = Wih[i];
    }
    for (int i = t; i < 32*64; i += 256) {
        int n = i >> 6, k = i & 63;
        h2s[n*68 + k] = g_h2[(nbase + n)*64 + k];
    }
    __syncthreads();
    float acc[8][4];
    #pragma unroll
    for (int q = 0; q < 8; q++) { acc[q][0]=0; acc[q][1]=0; acc[q][2]=0; acc[q][3]=0; }
    int j0 = cg*4;
    for (int k = 0; k < 64; k++) {
        float4 w = *(const float4*)&WT[k*260 + j0];
        #pragma unroll
        for (int q = 0; q < 8; q++) {
            float hv = h2s[(ng*8 + q)*68 + k];
            acc[q][0] += hv*w.x; acc[q][1] += hv*w.y;
            acc[q][2] += hv*w.z; acc[q][3] += hv*w.w;
        }
    }
    float4 bb;
    bb.x = bih[j0]   + bhh[j0];
    bb.y = bih[j0+1] + bhh[j0+1];
    bb.z = bih[j0+2] + bhh[j0+2];
    bb.w = bih[j0+3] + bhh[j0+3];
    #pragma unroll
    for (int q = 0; q < 8; q++) {
        int n = nbase + ng*8 + q;
        int dest = (ntime[n]*G_GRAPHS + batch[n])*C1 + j0;
        *(float4*)&g_xgates[dest] = make_float4(acc[q][0]+bb.x, acc[q][1]+bb.y,
                                                acc[q][2]+bb.z, acc[q][3]+bb.w);
    }
}

// 4 graphs per block; 50 sequential steps on-chip; fused final FC.
#define LPG 4
__global__ void k_lstm(const float* __restrict__ Whh, const float* __restrict__ Wfc,
                       const float* __restrict__ bfc, float* __restrict__ out) {
    extern __shared__ float sm[];
    float* WT   = sm;                 // [64 k][260 pad] = Whh^T
    float* hh   = sm + 64*260;        // [4][68]
    float* gate = hh + 4*68;          // [4][260]
    int t = threadIdx.x;
    int gbase = blockIdx.x * LPG;
    for (int i = t; i < 256*64; i += 256) {
        int j = i >> 6, k = i & 63;
        WT[k*260 + j] = Whh[i];
    }
    for (int i = t; i < 4*68; i += 256) hh[i] = 0.f;
    int gc = t >> 6, ic = t & 63;     // cell role
    float c = 0.f;
    __syncthreads();
    for (int step = 0; step < T_STEPS; step++) {
        float acc[LPG];
        const float* xg = &g_xgates[(step*G_GRAPHS + gbase)*C1 + t];
        #pragma unroll
        for (int g = 0; g < LPG; g++) acc[g] = xg[g*C1];
        for (int k = 0; k < 64; k++) {
            float w = WT[k*260 + t];
            #pragma unroll
            for (int g = 0; g < LPG; g++) acc[g] += hh[g*68 + k] * w;
        }
        #pragma unroll
        for (int g = 0; g < LPG; g++) gate[g*260 + t] = acc[g];
        __syncthreads();
        {
            float ig = gate[gc*260 + ic],      fg = gate[gc*260 + 64 + ic];
            float gg = gate[gc*260 + 128 + ic], og = gate[gc*260 + 192 + ic];
            c = sigf(fg)*c + sigf(ig)*tanhf(gg);
            hh[gc*68 + ic] = sigf(og)*tanhf(c);
        }
        __syncthreads();
    }
    if (t < LPG*OUT_DIM) {
        int g = t / OUT_DIM, o = t % OUT_DIM;
        float acc = bfc[o];
        #pragma unroll 8
        for (int k = 0; k < 64; k++) acc += hh[g*68 + k] * Wfc[k*OUT_DIM + o];
        out[(gbase + g)*OUT_DIM + o] = acc;
    }
}

// ---------------- launch ----------------
static const int SMEM_PROJ2 = (256*64 + 64*260) * 4;        // 132096
static const int SMEM_XG    = (64*260 + 32*68) * 4;         // 75264
static const int SMEM_LSTM  = (64*260 + 4*68 + 4*260) * 4;  // 71808

extern "C" void kernel_launch(void* const* d_in, const int* in_sizes, int n_in,
                              void* d_out, int out_size) {
    const float* x    = (const float*)d_in[0];
    const int*   ei   = (const int*)  d_in[1];
    const int*   batch= (const int*)  d_in[2];
    const int*   ntime= (const int*)  d_in[3];
    const float* W1   = (const float*)d_in[4];
    const float* as1  = (const float*)d_in[5];
    const float* ad1  = (const float*)d_in[6];
    const float* b1   = (const float*)d_in[7];
    const float* g1   = (const float*)d_in[8];
    const float* be1  = (const float*)d_in[9];
    const float* W2   = (const float*)d_in[10];
    const float* as2  = (const float*)d_in[11];
    const float* ad2  = (const float*)d_in[12];
    const float* b2   = (const float*)d_in[13];
    const float* g2   = (const float*)d_in[14];
    const float* be2  = (const float*)d_in[15];
    const float* Wih  = (const float*)d_in[16];
    const float* Whh  = (const float*)d_in[17];
    const float* bih  = (const float*)d_in[18];
    const float* bhh  = (const float*)d_in[19];
    const float* Wfc  = (const float*)d_in[20];
    const float* bfc  = (const float*)d_in[21];
    float* out = (float*)d_out;

    cudaFuncSetAttribute(k_proj2,  cudaFuncAttributeMaxDynamicSharedMemorySize, SMEM_PROJ2);
    cudaFuncSetAttribute(k_xgates, cudaFuncAttributeMaxDynamicSharedMemorySize, SMEM_XG);
    cudaFuncSetAttribute(k_lstm,   cudaFuncAttributeMaxDynamicSharedMemorySize, SMEM_LSTM);

    k_init  <<<(N_NODES*HID + 255)/256, 256>>>();
    k_pre1  <<<1, 64>>>(W1, as1, ad1);
    k_att1  <<<(N_NODES + 255)/256, 256>>>(x);
    k_esum1 <<<(ETOT + 255)/256, 256>>>(ei, x);
    k_fin1  <<<(N_NODES*C1 + 255)/256, 256>>>(W1, b1, g1, be1);
    k_proj2 <<<N_NODES/64, 256, SMEM_PROJ2>>>(W2);
    k_att2  <<<(N_NODES*32 + 255)/256, 256>>>(as2, ad2);
    k_esum2 <<<(ETOT*16 + 255)/256, 256>>>(ei);
    k_fin2  <<<(N_NODES*HID + 255)/256, 256>>>(b2, g2, be2);
    k_xgates<<<N_NODES/32, 256, SMEM_XG>>>(Wih, bih, bhh, batch, ntime);
    k_lstm  <<<G_GRAPHS/LPG, 256, SMEM_LSTM>>>(Whh, Wfc, bfc, out);
}

// round 3
// speedup vs baseline: 1.7773x; 1.0164x over previous
#include <cuda_runtime.h>
#include <math.h>

#define N_NODES 25600
#define N_EDGES 204800
#define ETOT    (N_EDGES + N_NODES)   // 230400
#define IN_CH   6
#define HID     64
#define HEADS   4
#define C1      (HEADS*HID)           // 256
#define G_GRAPHS 512
#define T_STEPS  50
#define OUT_DIM  30
#define NEG_SLOPE 0.2f
#define BN_INV 0.9999950000374996f    // 1/sqrt(1+1e-5)

// ---------------- scratch ----------------
__device__ float g_wsrc[24];                  // [k][h]
__device__ float g_wdst[24];
__device__ __align__(16) float g_x8[N_NODES*8];       // padded x rows
__device__ __align__(16) float g_asrc1[N_NODES*4];
__device__ __align__(16) float g_adst1[N_NODES*4];
__device__ __align__(16) float g_xagg[N_NODES*32];    // 4 heads x [x0..x5, denom, 0]
__device__ __align__(16) float g_hproj2[N_NODES*HID];
__device__ float g_asrc2[N_NODES];
__device__ float g_adst2[N_NODES];
__device__ float g_denom2[N_NODES];
__device__ __align__(16) float g_accum2[N_NODES*HID];
__device__ __align__(16) float g_xgates[N_NODES*C1];  // (t, g, 256)

// ---------------- helpers ----------------
__device__ __forceinline__ float lrelu(float v) { return v > 0.f ? v : NEG_SLOPE*v; }
__device__ __forceinline__ float eluf(float v)  { return v > 0.f ? v : expm1f(v); }
__device__ __forceinline__ float sigf(float v)  { return 1.f/(1.f+expf(-v)); }

__device__ __forceinline__ void redAdd4(float* addr, float a, float b, float c, float d) {
    asm volatile("red.global.add.v4.f32 [%0], {%1,%2,%3,%4};"
                 :: "l"(addr), "f"(a), "f"(b), "f"(c), "f"(d) : "memory");
}
// packed f32x2 fma: d = a*b + d (lane-wise)
__device__ __forceinline__ void ffma2(unsigned long long& d, unsigned long long a,
                                      unsigned long long b) {
    asm("fma.rn.f32x2 %0, %1, %2, %0;" : "+l"(d) : "l"(a), "l"(b));
}
__device__ __forceinline__ unsigned long long pk(float a, float b) {
    unsigned long long r;
    asm("mov.b64 %0, {%1, %2};" : "=l"(r) : "f"(a), "f"(b));
    return r;
}
__device__ __forceinline__ float2 unpk(unsigned long long v) {
    float2 r;
    asm("mov.b64 {%0, %1}, %2;" : "=f"(r.x), "=f"(r.y) : "l"(v));
    return r;
}

// ---------------- kernels ----------------
// wsrc[k][h] = sum_c W1[k, h*64+c]*att_src[h,c]
__global__ void k_pre1(const float* __restrict__ W1, const float* __restrict__ as1,
                       const float* __restrict__ ad1) {
    int t = threadIdx.x;
    if (t < 24) {
        int k = t >> 2, h = t & 3;
        float s = 0.f;
        for (int c = 0; c < 64; c++) s += W1[k*C1 + h*64 + c] * as1[h*64 + c];
        g_wsrc[t] = s;
    } else if (t >= 32 && t < 56) {
        int i = t - 32, k = i >> 2, h = i & 3;
        float s = 0.f;
        for (int c = 0; c < 64; c++) s += W1[k*C1 + h*64 + c] * ad1[h*64 + c];
        g_wdst[i] = s;
    }
}

// per-node attention dots + padded x copy
__global__ void k_att1(const float* __restrict__ x) {
    int n = blockIdx.x*blockDim.x + threadIdx.x;
    if (n >= N_NODES) return;
    float2 xa = *(const float2*)&x[n*6];
    float2 xb = *(const float2*)&x[n*6 + 2];
    float2 xc = *(const float2*)&x[n*6 + 4];
    float xv[6] = {xa.x, xa.y, xb.x, xb.y, xc.x, xc.y};
    float s[4] = {0,0,0,0}, d[4] = {0,0,0,0};
    #pragma unroll
    for (int k = 0; k < 6; k++) {
        #pragma unroll
        for (int h = 0; h < 4; h++) {
            s[h] += xv[k]*g_wsrc[k*4+h];
            d[h] += xv[k]*g_wdst[k*4+h];
        }
    }
    *(float4*)&g_asrc1[n*4] = make_float4(s[0],s[1],s[2],s[3]);
    *(float4*)&g_adst1[n*4] = make_float4(d[0],d[1],d[2],d[3]);
    *(float4*)&g_x8[n*8]     = make_float4(xv[0],xv[1],xv[2],xv[3]);
    *(float4*)&g_x8[n*8 + 4] = make_float4(xv[4],xv[5],0.f,0.f);
}

// per edge: ex[h]=exp(lrelu(.)); xagg[dst][h] += ex*{x, slot6: ex}
__global__ void k_esum1(const int* __restrict__ ei) {
    int e = blockIdx.x*blockDim.x + threadIdx.x;
    if (e >= ETOT) return;
    int s, d;
    if (e < N_EDGES) { s = ei[e]; d = ei[N_EDGES + e]; } else { s = d = e - N_EDGES; }
    float4 as = *(const float4*)&g_asrc1[s*4];
    float4 ad = *(const float4*)&g_adst1[d*4];
    float ex[4];
    ex[0] = expf(lrelu(as.x + ad.x));
    ex[1] = expf(lrelu(as.y + ad.y));
    ex[2] = expf(lrelu(as.z + ad.z));
    ex[3] = expf(lrelu(as.w + ad.w));
    float4 xa = *(const float4*)&g_x8[s*8];
    float4 xb = *(const float4*)&g_x8[s*8 + 4];
    float* base = &g_xagg[d*32];
    #pragma unroll
    for (int h = 0; h < 4; h++) {
        float w = ex[h];
        redAdd4(base + h*8,     w*xa.x, w*xa.y, w*xa.z, w*xa.w);
        redAdd4(base + h*8 + 4, w*xb.x, w*xb.y, w,      0.f);
    }
}

// fused: h1 = elu(bn(xagg@W1/denom)); hproj2 = h1@W2; att2 dots
#define P2N 64
__global__ void __launch_bounds__(256) k_proj2f(
        const float* __restrict__ W1, const float* __restrict__ b1,
        const float* __restrict__ g1, const float* __restrict__ be1,
        const float* __restrict__ W2,
        const float* __restrict__ as2, const float* __restrict__ ad2) {
    extern __shared__ float sm[];
    float* W2p  = sm;                  // [128 k2][64 j][2] = 16384
    float* h1s  = sm + 16384;          // [64][258]
    float* xags = h1s + P2N*258;       // [64][32]
    int t = threadIdx.x;
    int nbase = blockIdx.x * P2N;

    for (int i = t; i < 16384; i += 256) {
        int k = i >> 6, j = i & 63;
        W2p[(k >> 1)*128 + j*2 + (k & 1)] = W2[i];
    }
    for (int i = t; i < P2N*32; i += 256) xags[i] = g_xagg[nbase*32 + i];
    __syncthreads();

    { // h1 tile: column c = t fixed per thread
        float w1r[6];
        #pragma unroll
        for (int k = 0; k < 6; k++) w1r[k] = W1[k*C1 + t];
        float b1r = b1[t], g1r = g1[t]*BN_INV, ber = be1[t];
        int h = t >> 6;
        for (int n = 0; n < P2N; n++) {
            const float* xa = &xags[n*32 + h*8];
            float v = 0.f;
            #pragma unroll
            for (int k = 0; k < 6; k++) v += xa[k]*w1r[k];
            v = v/xa[6] + b1r;
            h1s[n*258 + t] = eluf(g1r*v + ber);
        }
    }
    __syncthreads();

    int cg = t & 15, ng = t >> 4;
    int j0 = cg*4;
    unsigned long long acc[4][4];
    #pragma unroll
    for (int q = 0; q < 4; q++)
        #pragma unroll
        for (int j = 0; j < 4; j++) acc[q][j] = 0ull;

    for (int k2 = 0; k2 < 128; k2++) {
        const float* wb = &W2p[k2*128 + j0*2];
        ulonglong2 w01 = *(const ulonglong2*)wb;
        ulonglong2 w23 = *(const ulonglong2*)(wb + 4);
        #pragma unroll
        for (int q = 0; q < 4; q++) {
            unsigned long long hv = *(const unsigned long long*)&h1s[(ng*4 + q)*258 + k2*2];
            ffma2(acc[q][0], hv, w01.x);
            ffma2(acc[q][1], hv, w01.y);
            ffma2(acc[q][2], hv, w23.x);
            ffma2(acc[q][3], hv, w23.y);
        }
    }

    float as2r[4], ad2r[4];
    #pragma unroll
    for (int j = 0; j < 4; j++) { as2r[j] = as2[j0+j]; ad2r[j] = ad2[j0+j]; }
    #pragma unroll
    for (int q = 0; q < 4; q++) {
        float o[4], s = 0.f, dd = 0.f;
        #pragma unroll
        for (int j = 0; j < 4; j++) {
            float2 u = unpk(acc[q][j]);
            o[j] = u.x + u.y;
            s  += o[j]*as2r[j];
            dd += o[j]*ad2r[j];
        }
        int n = nbase + ng*4 + q;
        *(float4*)&g_hproj2[n*64 + j0] = make_float4(o[0],o[1],o[2],o[3]);
        #pragma unroll
        for (int m = 1; m < 16; m <<= 1) {
            s  += __shfl_xor_sync(~0u, s,  m);
            dd += __shfl_xor_sync(~0u, dd, m);
        }
        if (cg == 0) { g_asrc2[n] = s; g_adst2[n] = dd; }
    }
}

// 8 threads/edge: denom += ex; accum2[dst] += ex*hproj2[src]
__global__ void k_esum2(const int* __restrict__ ei) {
    int gt = blockIdx.x*blockDim.x + threadIdx.x;
    int e = gt >> 3, q = gt & 7;
    if (e >= ETOT) return;
    int s, d;
    if (e < N_EDGES) { s = ei[e]; d = ei[N_EDGES + e]; } else { s = d = e - N_EDGES; }
    float ex = expf(lrelu(g_asrc2[s] + g_adst2[d]));
    if (q == 0) atomicAdd(&g_denom2[d], ex);
    int c = q*8;
    float4 v1 = *(const float4*)&g_hproj2[s*64 + c];
    float4 v2 = *(const float4*)&g_hproj2[s*64 + c + 4];
    redAdd4(&g_accum2[d*64 + c],     v1.x*ex, v1.y*ex, v1.z*ex, v1.w*ex);
    redAdd4(&g_accum2[d*64 + c + 4], v2.x*ex, v2.y*ex, v2.z*ex, v2.w*ex);
}

// fused: h2 = elu(bn(accum2/denom2)); xgates = h2@Wih^T + bih + bhh (scattered)
#define XGN 32
__global__ void __launch_bounds__(256, 2) k_xgates2(
        const float* __restrict__ Wih, const float* __restrict__ bih,
        const float* __restrict__ bhh, const float* __restrict__ b2,
        const float* __restrict__ g2, const float* __restrict__ be2,
        const int* __restrict__ batch, const int* __restrict__ ntime) {
    extern __shared__ float sm[];
    float* WTp = sm;                   // [32 k2][256 j][2] = 16384
    float* h2s = sm + 16384;           // [32][66]
    int t = threadIdx.x;
    int nbase = blockIdx.x * XGN;

    for (int i = t; i < 16384; i += 256) {
        int j = i >> 6, k = i & 63;
        WTp[(k >> 1)*512 + j*2 + (k & 1)] = Wih[i];
    }
    {
        int k = t & 63;
        float b2r = b2[k], g2r = g2[k]*BN_INV, ber = be2[k];
        for (int i = t; i < XGN*64; i += 256) {
            int n = i >> 6;
            float v = g_accum2[(nbase + n)*64 + k] / g_denom2[nbase + n] + b2r;
            h2s[n*66 + k] = eluf(g2r*v + ber);
        }
    }
    __syncthreads();

    int cg = t & 63, ng = t >> 6;
    int j0 = cg*4;
    unsigned long long acc[8][4];
    #pragma unroll
    for (int q = 0; q < 8; q++)
        #pragma unroll
        for (int j = 0; j < 4; j++) acc[q][j] = 0ull;

    #pragma unroll 4
    for (int k2 = 0; k2 < 32; k2++) {
        const float* wb = &WTp[k2*512 + j0*2];
        ulonglong2 w01 = *(const ulonglong2*)wb;
        ulonglong2 w23 = *(const ulonglong2*)(wb + 4);
        #pragma unroll
        for (int q = 0; q < 8; q++) {
            unsigned long long hv = *(const unsigned long long*)&h2s[(ng*8 + q)*66 + k2*2];
            ffma2(acc[q][0], hv, w01.x);
            ffma2(acc[q][1], hv, w01.y);
            ffma2(acc[q][2], hv, w23.x);
            ffma2(acc[q][3], hv, w23.y);
        }
    }

    float4 bb;
    bb.x = bih[j0]   + bhh[j0];
    bb.y = bih[j0+1] + bhh[j0+1];
    bb.z = bih[j0+2] + bhh[j0+2];
    bb.w = bih[j0+3] + bhh[j0+3];
    #pragma unroll
    for (int q = 0; q < 8; q++) {
        int n = nbase + ng*8 + q;
        float2 u0 = unpk(acc[q][0]), u1 = unpk(acc[q][1]);
        float2 u2 = unpk(acc[q][2]), u3 = unpk(acc[q][3]);
        int dest = (ntime[n]*G_GRAPHS + batch[n])*C1 + j0;
        *(float4*)&g_xgates[dest] = make_float4(u0.x+u0.y+bb.x, u1.x+u1.y+bb.y,
                                                u2.x+u2.y+bb.z, u3.x+u3.y+bb.w);
    }
}

// LSTM: 4 graphs/block, Whh row in registers (packed f32x2), fused final FC
#define LPG 4
__global__ void __launch_bounds__(256) k_lstm(
        const float* __restrict__ Whh, const float* __restrict__ Wfc,
        const float* __restrict__ bfc, float* __restrict__ out) {
    __shared__ float hhs[LPG*64];
    __shared__ float gates[LPG*C1];
    int t = threadIdx.x;
    int gbase = blockIdx.x * LPG;

    unsigned long long w2[32];
    const float4* wrow = (const float4*)(Whh + t*64);
    #pragma unroll
    for (int i = 0; i < 16; i++) {
        float4 w = wrow[i];
        w2[2*i]   = pk(w.x, w.y);
        w2[2*i+1] = pk(w.z, w.w);
    }
    for (int i = t; i < LPG*64; i += 256) hhs[i] = 0.f;
    int gc = t >> 6, ic = t & 63;
    float c = 0.f;
    __syncthreads();

    for (int step = 0; step < T_STEPS; step++) {
        unsigned long long aA[LPG], aB[LPG];
        #pragma unroll
        for (int g = 0; g < LPG; g++) { aA[g] = 0ull; aB[g] = 0ull; }
        #pragma unroll
        for (int k2 = 0; k2 < 16; k2++) {      // 4 k per iteration
            #pragma unroll
            for (int g = 0; g < LPG; g++) {
                ulonglong2 hv = *(const ulonglong2*)&hhs[g*64 + k2*4];
                ffma2(aA[g], hv.x, w2[2*k2]);
                ffma2(aB[g], hv.y, w2[2*k2+1]);
            }
        }
        const float* xg = &g_xgates[(step*G_GRAPHS + gbase)*C1 + t];
        #pragma unroll
        for (int g = 0; g < LPG; g++) {
            float2 a = unpk(aA[g]), b = unpk(aB[g]);
            gates[g*C1 + t] = xg[g*C1] + a.x + a.y + b.x + b.y;
        }
        __syncthreads();
        {
            float ig = gates[gc*C1 + ic],       fg = gates[gc*C1 + 64 + ic];
            float gg = gates[gc*C1 + 128 + ic], og = gates[gc*C1 + 192 + ic];
            c = sigf(fg)*c + sigf(ig)*tanhf(gg);
            hhs[gc*64 + ic] = sigf(og)*tanhf(c);
        }
        __syncthreads();
    }
    if (t < LPG*OUT_DIM) {
        int g = t / OUT_DIM, o = t % OUT_DIM;
        float acc = bfc[o];
        #pragma unroll 8
        for (int k = 0; k < 64; k++) acc += hhs[g*64 + k] * Wfc[k*OUT_DIM + o];
        out[(gbase + g)*OUT_DIM + o] = acc;
    }
}

// ---------------- launch ----------------
static const int SMEM_P2 = (16384 + P2N*258 + P2N*32) * 4;   // ~139.8 KB
static const int SMEM_XG = (16384 + XGN*66) * 4;             // ~74 KB

extern "C" void kernel_launch(void* const* d_in, const int* in_sizes, int n_in,
                              void* d_out, int out_size) {
    const float* x    = (const float*)d_in[0];
    const int*   ei   = (const int*)  d_in[1];
    const int*   batch= (const int*)  d_in[2];
    const int*   ntime= (const int*)  d_in[3];
    const float* W1   = (const float*)d_in[4];
    const float* as1  = (const float*)d_in[5];
    const float* ad1  = (const float*)d_in[6];
    const float* b1   = (const float*)d_in[7];
    const float* g1   = (const float*)d_in[8];
    const float* be1  = (const float*)d_in[9];
    const float* W2   = (const float*)d_in[10];
    const float* as2  = (const float*)d_in[11];
    const float* ad2  = (const float*)d_in[12];
    const float* b2   = (const float*)d_in[13];
    const float* g2   = (const float*)d_in[14];
    const float* be2  = (const float*)d_in[15];
    const float* Wih  = (const float*)d_in[16];
    const float* Whh  = (const float*)d_in[17];
    const float* bih  = (const float*)d_in[18];
    const float* bhh  = (const float*)d_in[19];
    const float* Wfc  = (const float*)d_in[20];
    const float* bfc  = (const float*)d_in[21];
    float* out = (float*)d_out;

    cudaFuncSetAttribute(k_proj2f,  cudaFuncAttributeMaxDynamicSharedMemorySize, SMEM_P2);
    cudaFuncSetAttribute(k_xgates2, cudaFuncAttributeMaxDynamicSharedMemorySize, SMEM_XG);

    void *p_xagg, *p_acc2, *p_den2;
    cudaGetSymbolAddress(&p_xagg, g_xagg);
    cudaGetSymbolAddress(&p_acc2, g_accum2);
    cudaGetSymbolAddress(&p_den2, g_denom2);
    cudaMemsetAsync(p_xagg, 0, sizeof(float)*N_NODES*32);
    cudaMemsetAsync(p_acc2, 0, sizeof(float)*N_NODES*HID);
    cudaMemsetAsync(p_den2, 0, sizeof(float)*N_NODES);

    k_pre1   <<<1, 64>>>(W1, as1, ad1);
    k_att1   <<<(N_NODES + 255)/256, 256>>>(x);
    k_esum1  <<<(ETOT + 255)/256, 256>>>(ei);
    k_proj2f <<<N_NODES/P2N, 256, SMEM_P2>>>(W1, b1, g1, be1, W2, as2, ad2);
    k_esum2  <<<(ETOT*8 + 255)/256, 256>>>(ei);
    k_xgates2<<<N_NODES/XGN, 256, SMEM_XG>>>(Wih, bih, bhh, b2, g2, be2, batch, ntime);
    k_lstm   <<<G_GRAPHS/LPG, 256>>>(Whh, Wfc, bfc, out);
}